// round 2
// baseline (speedup 1.0000x reference)
#include <cuda_runtime.h>
#include <math.h>
#include <stdint.h>

// Problem constants
static constexpr int kB  = 64;      // batch
static constexpr int kT  = 1024;    // time steps
static constexpr int kF  = 512;     // input features
static constexpr int kU  = 1024;    // hidden units
static constexpr int k4U = 4096;    // 4*U (gates i,f,g,o)
static constexpr int kC  = 1000;    // classes

// LSTM kernel config
static constexpr int NCTA = 128;    // persistent CTAs (<= 148 SMs, 1 CTA/SM)
static constexpr int NTHR = 128;    // threads per CTA
static constexpr int UPC  = 8;      // hidden units per CTA (128*8 = 1024)
static constexpr int WPAD = 1028;   // padded K-stride for Wr in smem (bank-friendly)

// Scratch (device globals: allocation-free per harness rules)
__device__ float    g_xz[(size_t)kB * kT * k4U];   // 1 GiB: precomputed x@Wk + b
__device__ float    g_h[2 * kB * kU];              // ping-pong hidden state
__device__ unsigned g_arrive;                      // grid barrier counter

// ---------------------------------------------------------------------------
// Kernel 0: reset state so every graph replay is deterministic
// ---------------------------------------------------------------------------
__global__ void reset_kernel() {
    int idx = blockIdx.x * blockDim.x + threadIdx.x;
    if (idx == 0) g_arrive = 0u;
    for (int i = idx; i < 2 * kB * kU; i += gridDim.x * blockDim.x) g_h[i] = 0.f;
}

// ---------------------------------------------------------------------------
// Kernel 1: xz[m][g] = sum_f x[m][f] * Wk[f][g] + b[g]
// Classic 128x128x8 fp32 SMEM GEMM, 256 threads, 8x8 micro-tile.
// M = 65536 (b*T + t), N = 4096, K = 512.
// ---------------------------------------------------------------------------
__global__ __launch_bounds__(256) void gemm_xz_kernel(
    const float* __restrict__ x, const float* __restrict__ Wk,
    const float* __restrict__ bias) {
    __shared__ float As[8][128];   // As[k][m]
    __shared__ float Bs[8][128];   // Bs[k][n]

    const int tid = threadIdx.x;
    const int tx  = tid & 15;
    const int ty  = tid >> 4;
    const int n0  = blockIdx.x * 128;
    const int m0  = blockIdx.y * 128;

    const int arow = tid >> 1;
    const int aseg = (tid & 1) * 4;
    const int brow = tid >> 5;
    const int bcol = (tid & 31) * 4;

    const float* xg = x  + (size_t)(m0 + arow) * kF + aseg;
    const float* wg = Wk + (size_t)brow * k4U + n0 + bcol;

    float acc[8][8];
#pragma unroll
    for (int i = 0; i < 8; i++)
#pragma unroll
        for (int j = 0; j < 8; j++) acc[i][j] = 0.f;

    for (int k0 = 0; k0 < kF; k0 += 8) {
        float4 av = *(const float4*)(xg + k0);
        float4 bv = *(const float4*)(wg + (size_t)k0 * k4U);
        __syncthreads();
        As[aseg + 0][arow] = av.x;
        As[aseg + 1][arow] = av.y;
        As[aseg + 2][arow] = av.z;
        As[aseg + 3][arow] = av.w;
        *(float4*)&Bs[brow][bcol] = bv;
        __syncthreads();
#pragma unroll
        for (int kk = 0; kk < 8; kk++) {
            float a[8], b[8];
            *(float4*)&a[0] = *(const float4*)&As[kk][ty * 8];
            *(float4*)&a[4] = *(const float4*)&As[kk][ty * 8 + 4];
            *(float4*)&b[0] = *(const float4*)&Bs[kk][tx * 8];
            *(float4*)&b[4] = *(const float4*)&Bs[kk][tx * 8 + 4];
#pragma unroll
            for (int i = 0; i < 8; i++)
#pragma unroll
                for (int j = 0; j < 8; j++)
                    acc[i][j] = fmaf(a[i], b[j], acc[i][j]);
        }
    }

    float bb[8];
    *(float4*)&bb[0] = *(const float4*)&bias[n0 + tx * 8];
    *(float4*)&bb[4] = *(const float4*)&bias[n0 + tx * 8 + 4];
#pragma unroll
    for (int i = 0; i < 8; i++) {
        float* orow = g_xz + (size_t)(m0 + ty * 8 + i) * k4U + n0 + tx * 8;
        float4 v0 = make_float4(acc[i][0] + bb[0], acc[i][1] + bb[1],
                                acc[i][2] + bb[2], acc[i][3] + bb[3]);
        float4 v1 = make_float4(acc[i][4] + bb[4], acc[i][5] + bb[5],
                                acc[i][6] + bb[6], acc[i][7] + bb[7]);
        *(float4*)orow       = v0;
        *(float4*)(orow + 4) = v1;
    }
}

// ---------------------------------------------------------------------------
// Kernel 2: persistent LSTM recurrence.
// CTA i owns hidden units u in [8i, 8i+8). Its 32 z-columns are
// {q*1024 + u_base + j : q in 0..3, j in 0..7}, local index c = q*8 + j.
// Wr slice (32 cols x 1024 K, 128 KB) staged in SMEM once; cell state c in
// SMEM for the whole kernel; h ping-pongs in global with one grid barrier/step.
// ---------------------------------------------------------------------------
extern __shared__ float lstm_smem[];

__global__ __launch_bounds__(NTHR, 1) void lstm_kernel(const float* __restrict__ Wr) {
    float* Wr_s = lstm_smem;                 // [32][WPAD]
    float* h_s  = Wr_s + 32 * WPAD;          // [64][64] chunk of h
    float* z_s  = h_s + 64 * 64;             // [64][33]
    float* c_s  = z_s + 64 * 33;             // [64][8]

    const int tid    = threadIdx.x;
    const int cta    = blockIdx.x;
    const int u_base = cta * UPC;

    // Stage Wr slice: Wr_s[c][k] = Wr[k][ (c>>3)*1024 + u_base + (c&7) ]
    for (int i = 0; i < (32 * kU) / NTHR; i++) {
        int lin = tid + i * NTHR;
        int c   = lin & 31;
        int k   = lin >> 5;
        int gcol = ((c >> 3) << 10) + u_base + (c & 7);
        Wr_s[c * WPAD + k] = Wr[(size_t)k * k4U + gcol];
    }
    for (int i = tid; i < kB * UPC; i += NTHR) c_s[i] = 0.f;
    __syncthreads();

    // Micro-tile: thread -> cols {cA, cA+16}, rows [rb, rb+8)
    const int cA = tid & 15;
    const int cB = cA + 16;
    const int rb = (tid >> 4) * 8;

    for (int t = 0; t < kT; t++) {
        const float* hread  = g_h + (size_t)(t & 1) * (kB * kU);
        float*       hwrite = g_h + (size_t)((t + 1) & 1) * (kB * kU);

        float acc0[8], acc1[8];
#pragma unroll
        for (int r = 0; r < 8; r++) { acc0[r] = 0.f; acc1[r] = 0.f; }

        for (int kc = 0; kc < 16; kc++) {         // 16 chunks of 64 K each
            __syncthreads();                      // protect h_s reuse
#pragma unroll
            for (int i = 0; i < 8; i++) {         // stage h chunk [64][64]
                int lin = tid + i * NTHR;         // float4 slot 0..1023
                int row = lin >> 4;
                int kq  = lin & 15;
                // __ldcg: L2 path — h was written by other SMs this launch.
                float4 v = __ldcg((const float4*)(hread + (size_t)row * kU + kc * 64 + kq * 4));
                *(float4*)(h_s + row * 64 + kq * 4) = v;
            }
            __syncthreads();

            const float* wA = Wr_s + cA * WPAD + kc * 64;
            const float* wB = Wr_s + cB * WPAD + kc * 64;
#pragma unroll 4
            for (int kk4 = 0; kk4 < 16; kk4++) {
                float4 wa = *(const float4*)(wA + kk4 * 4);
                float4 wb = *(const float4*)(wB + kk4 * 4);
#pragma unroll
                for (int r = 0; r < 8; r++) {
                    float4 hv = *(const float4*)(h_s + (rb + r) * 64 + kk4 * 4);
                    acc0[r] = fmaf(hv.x, wa.x, acc0[r]);
                    acc0[r] = fmaf(hv.y, wa.y, acc0[r]);
                    acc0[r] = fmaf(hv.z, wa.z, acc0[r]);
                    acc0[r] = fmaf(hv.w, wa.w, acc0[r]);
                    acc1[r] = fmaf(hv.x, wb.x, acc1[r]);
                    acc1[r] = fmaf(hv.y, wb.y, acc1[r]);
                    acc1[r] = fmaf(hv.z, wb.z, acc1[r]);
                    acc1[r] = fmaf(hv.w, wb.w, acc1[r]);
                }
            }
        }

        // Publish z tile to smem
#pragma unroll
        for (int r = 0; r < 8; r++) {
            z_s[(rb + r) * 33 + cA] = acc0[r];
            z_s[(rb + r) * 33 + cB] = acc1[r];
        }
        __syncthreads();

        // Gate phase: 512 cells (b, j), 4 per thread
#pragma unroll
        for (int s = 0; s < 4; s++) {
            int cell = tid + s * NTHR;
            int b = cell >> 3;
            int j = cell & 7;
            const float* xzp = g_xz + ((size_t)b * kT + t) * k4U + u_base + j;
            float zi = z_s[b * 33 + j]          + xzp[0];
            float zf = z_s[b * 33 + 8 + j]      + xzp[kU];
            float zg = z_s[b * 33 + 16 + j]     + xzp[2 * kU];
            float zo = z_s[b * 33 + 24 + j]     + xzp[3 * kU];
            float ig = 1.f / (1.f + expf(-zi));
            float fg = 1.f / (1.f + expf(-zf));
            float gg = tanhf(zg);
            float og = 1.f / (1.f + expf(-zo));
            float cv = fg * c_s[b * UPC + j] + ig * gg;
            c_s[b * UPC + j] = cv;
            hwrite[(size_t)b * kU + u_base + j] = og * tanhf(cv);
        }

        // Grid barrier (monotonic counter, reset to 0 each replay)
        __syncthreads();
        __threadfence();
        if (tid == 0) {
            atomicAdd(&g_arrive, 1u);
            unsigned target = (unsigned)(t + 1) * NCTA;
            while (*((volatile unsigned*)&g_arrive) < target) { }
        }
        __syncthreads();
        __threadfence();
    }
}

// ---------------------------------------------------------------------------
// Kernel 3: logits = h_last @ Wd + bd; softmax per row.
// One CTA per batch row; thread handles 4 consecutive classes.
// Final h lives in g_h buffer 0 (t=1023 writes buffer (1024&1)=0).
// ---------------------------------------------------------------------------
__global__ __launch_bounds__(256) void dense_softmax_kernel(
    const float* __restrict__ Wd, const float* __restrict__ bd,
    float* __restrict__ out) {
    __shared__ float hrow[kU];
    __shared__ float red[256];

    const int b   = blockIdx.x;
    const int tid = threadIdx.x;
    const float* hsrc = g_h + (size_t)b * kU;    // buffer 0
    *(float4*)&hrow[tid * 4] = *(const float4*)&hsrc[tid * 4];
    __syncthreads();

    float acc[4] = {0.f, 0.f, 0.f, 0.f};
    const int j0 = tid * 4;
    const bool active = (j0 < kC);
    if (active) {
        const float* wp = Wd + j0;
#pragma unroll 4
        for (int k = 0; k < kU; k++) {
            float4 w  = *(const float4*)(wp + (size_t)k * kC);
            float  hk = hrow[k];
            acc[0] = fmaf(hk, w.x, acc[0]);
            acc[1] = fmaf(hk, w.y, acc[1]);
            acc[2] = fmaf(hk, w.z, acc[2]);
            acc[3] = fmaf(hk, w.w, acc[3]);
        }
        float4 bv = *(const float4*)&bd[j0];
        acc[0] += bv.x; acc[1] += bv.y; acc[2] += bv.z; acc[3] += bv.w;
    }

    // row max
    float m = active ? fmaxf(fmaxf(acc[0], acc[1]), fmaxf(acc[2], acc[3]))
                     : -INFINITY;
    red[tid] = m;
    __syncthreads();
    for (int s = 128; s > 0; s >>= 1) {
        if (tid < s) red[tid] = fmaxf(red[tid], red[tid + s]);
        __syncthreads();
    }
    float mx = red[0];
    __syncthreads();

    float e[4] = {0.f, 0.f, 0.f, 0.f};
    float psum = 0.f;
    if (active) {
#pragma unroll
        for (int c = 0; c < 4; c++) { e[c] = expf(acc[c] - mx); psum += e[c]; }
    }
    red[tid] = psum;
    __syncthreads();
    for (int s = 128; s > 0; s >>= 1) {
        if (tid < s) red[tid] += red[tid + s];
        __syncthreads();
    }
    float inv = 1.f / red[0];
    if (active) {
#pragma unroll
        for (int c = 0; c < 4; c++) out[(size_t)b * kC + j0 + c] = e[c] * inv;
    }
}

// ---------------------------------------------------------------------------
// Launch
// ---------------------------------------------------------------------------
extern "C" void kernel_launch(void* const* d_in, const int* in_sizes, int n_in,
                              void* d_out, int out_size) {
    const float* x    = (const float*)d_in[0];
    const float* Wk   = (const float*)d_in[1];
    const float* Wr   = (const float*)d_in[2];
    const float* bias = (const float*)d_in[3];
    const float* Wd   = (const float*)d_in[4];
    const float* bd   = (const float*)d_in[5];
    float* out = (float*)d_out;

    const int smem_bytes = (32 * WPAD + 64 * 64 + 64 * 33 + 64 * 8) * (int)sizeof(float);
    cudaFuncSetAttribute(lstm_kernel, cudaFuncAttributeMaxDynamicSharedMemorySize,
                         smem_bytes);

    reset_kernel<<<64, 256>>>();
    gemm_xz_kernel<<<dim3(k4U / 128, (kB * kT) / 128), 256>>>(x, Wk, bias);
    lstm_kernel<<<NCTA, NTHR, smem_bytes>>>(Wr);
    dense_softmax_kernel<<<kB, 256>>>(Wd, bd, out);
}

// round 3
// speedup vs baseline: 2.4695x; 2.4695x over previous
#include <cuda_runtime.h>
#include <math.h>
#include <stdint.h>

// Problem constants
static constexpr int kB  = 64;      // batch
static constexpr int kT  = 1024;    // time steps
static constexpr int kF  = 512;     // input features
static constexpr int kU  = 1024;    // hidden units
static constexpr int k4U = 4096;    // 4*U (gates i,f,g,o)
static constexpr int kC  = 1000;    // classes

static constexpr int NCTA = 128;    // persistent CTAs (1/SM)
static constexpr int NTHR = 128;    // threads (4 warps)

// Scratch (device globals: allocation-free per harness rules)
__device__ float    g_xz[(size_t)kB * kT * k4U];   // [T][B][4U] layout
__device__ float    g_h[2 * kB * kU];              // ping-pong hidden state
__device__ unsigned g_arrive;                      // grid barrier counter

__device__ __forceinline__ uint32_t f2tf32(float f) {
    uint32_t r;
    asm("cvt.rna.tf32.f32 %0, %1;" : "=r"(r) : "f"(f));
    return r;
}

__device__ __forceinline__ void mma_tf32(float c[4], uint32_t a0, uint32_t a1,
                                         uint32_t a2, uint32_t a3,
                                         uint32_t b0, uint32_t b1) {
    asm volatile(
        "mma.sync.aligned.m16n8k8.row.col.f32.tf32.tf32.f32 "
        "{%0,%1,%2,%3},{%4,%5,%6,%7},{%8,%9},{%0,%1,%2,%3};"
        : "+f"(c[0]), "+f"(c[1]), "+f"(c[2]), "+f"(c[3])
        : "r"(a0), "r"(a1), "r"(a2), "r"(a3), "r"(b0), "r"(b1));
}

// ---------------------------------------------------------------------------
// Kernel 0: reset state so every graph replay is deterministic
// ---------------------------------------------------------------------------
__global__ void reset_kernel() {
    int idx = blockIdx.x * blockDim.x + threadIdx.x;
    if (idx == 0) g_arrive = 0u;
    for (int i = idx; i < 2 * kB * kU; i += gridDim.x * blockDim.x) g_h[i] = 0.f;
}

// ---------------------------------------------------------------------------
// Kernel 1: xz = x@Wk + b  via tf32 mma.sync. Tile 128x128x16, 256 thr/8 warps,
// warp tile 32x64. Output written to g_xz in [T][B][4U] layout.
// SMEM: As[m][20] (16 used + 4 pad), Bs[k][136] (128 used + 8 pad) — both
// patterns give conflict-free fragment LDS (banks 20g+k / 8k+n are bijective).
// ---------------------------------------------------------------------------
__global__ __launch_bounds__(256) void gemm_xz_tf32(
    const float* __restrict__ x, const float* __restrict__ Wk,
    const float* __restrict__ bias) {
    __shared__ uint32_t As[128 * 20];
    __shared__ uint32_t Bs[16 * 136];

    const int tid = threadIdx.x;
    const int w   = tid >> 5, l = tid & 31;
    const int grp = l >> 2, qd = l & 3;
    const int mw  = (w & 3) * 32;
    const int nw  = (w >> 2) * 64;
    const int n0  = blockIdx.x * 128;
    const int m0  = blockIdx.y * 128;

    float acc[2][8][4];
#pragma unroll
    for (int i = 0; i < 2; i++)
#pragma unroll
        for (int j = 0; j < 8; j++)
#pragma unroll
            for (int k = 0; k < 4; k++) acc[i][j][k] = 0.f;

    for (int k0 = 0; k0 < kF; k0 += 16) {
        __syncthreads();
        // stage A (x tile 128x16)
#pragma unroll
        for (int i = 0; i < 2; i++) {
            int f   = tid + i * 256;           // float4 index < 512
            int row = f >> 2, ks = (f & 3) * 4;
            float4 v = *(const float4*)(x + (size_t)(m0 + row) * kF + k0 + ks);
            uint32_t* p = &As[row * 20 + ks];
            p[0] = f2tf32(v.x); p[1] = f2tf32(v.y);
            p[2] = f2tf32(v.z); p[3] = f2tf32(v.w);
        }
        // stage B (Wk tile 16x128)
#pragma unroll
        for (int i = 0; i < 2; i++) {
            int f  = tid + i * 256;
            int kk = f >> 5, ns = (f & 31) * 4;
            float4 v = *(const float4*)(Wk + (size_t)(k0 + kk) * k4U + n0 + ns);
            uint32_t* p = &Bs[kk * 136 + ns];
            p[0] = f2tf32(v.x); p[1] = f2tf32(v.y);
            p[2] = f2tf32(v.z); p[3] = f2tf32(v.w);
        }
        __syncthreads();

#pragma unroll
        for (int half = 0; half < 16; half += 8) {
            uint32_t a[2][4];
#pragma unroll
            for (int mt = 0; mt < 2; mt++) {
                int r = mw + mt * 16 + grp;
                a[mt][0] = As[r * 20 + half + qd];
                a[mt][1] = As[(r + 8) * 20 + half + qd];
                a[mt][2] = As[r * 20 + half + qd + 4];
                a[mt][3] = As[(r + 8) * 20 + half + qd + 4];
            }
#pragma unroll
            for (int nt = 0; nt < 8; nt++) {
                int n = nw + nt * 8 + grp;
                uint32_t b0 = Bs[(half + qd) * 136 + n];
                uint32_t b1 = Bs[(half + qd + 4) * 136 + n];
                mma_tf32(acc[0][nt], a[0][0], a[0][1], a[0][2], a[0][3], b0, b1);
                mma_tf32(acc[1][nt], a[1][0], a[1][1], a[1][2], a[1][3], b0, b1);
            }
        }
    }

    // Epilogue: add bias, write to g_xz[t][b][col]
#pragma unroll
    for (int nt = 0; nt < 8; nt++) {
        int col = n0 + nw + nt * 8 + 2 * qd;
        float2 bv = *(const float2*)(bias + col);
#pragma unroll
        for (int mt = 0; mt < 2; mt++) {
            int mg = m0 + mw + mt * 16 + grp;
#pragma unroll
            for (int ri = 0; ri < 2; ri++) {
                int row = mg + 8 * ri;
                int b = row >> 10;         // m = b*kT + t
                int t = row & 1023;
                float2 o;
                o.x = acc[mt][nt][2 * ri + 0] + bv.x;
                o.y = acc[mt][nt][2 * ri + 1] + bv.y;
                *(float2*)(g_xz + ((size_t)t * kB + b) * k4U + col) = o;
            }
        }
    }
}

// ---------------------------------------------------------------------------
// Kernel 2: persistent LSTM recurrence on tf32 mma.sync.
// CTA owns units [8*cta, 8*cta+8) -> 32 z-columns (4 gates x 8 units).
// Wr slice staged ONCE in B-fragment-permuted SMEM (128 KB).
// h staged per 128-K chunk into h_s[b][132] (conflict-free A-frag LDS).
// C fragment maps so each thread holds all 4 gates of its 4 cells:
// gate math + cell state fully in registers.
// ---------------------------------------------------------------------------
extern __shared__ uint32_t lstm_smem_u[];

__global__ __launch_bounds__(NTHR, 1) void lstm_tf32(const float* __restrict__ Wr) {
    uint32_t* Wr_f = lstm_smem_u;            // 4*128*32*2 = 32768 u32 (128 KB)
    uint32_t* h_s  = lstm_smem_u + 32768;    // 64*132 u32 (33 KB)

    const int tid = threadIdx.x;
    const int w = tid >> 5, l = tid & 31;
    const int grp = l >> 2, qd = l & 3;
    const int u_base = blockIdx.x * 8;
    const int b0 = w * 16 + grp;             // first of the thread's 2 batch rows
    const int j0 = 2 * qd;                   // first of the thread's 2 units

    // Stage Wr slice into fragment layout (one time)
    for (int i = 0; i < 256; i++) {
        int lin = tid + i * NTHR;            // 32768 values
        int c = lin & 31, k = lin >> 5;
        int q = c >> 3, j = c & 7;
        float v = Wr[(size_t)k * k4U + q * kU + u_base + j];
        int kc = k >> 3, kr = k & 7;
        int lane = (j << 2) | (kr & 3);
        int reg  = kr >> 2;
        Wr_f[((q * 128 + kc) * 32 + lane) * 2 + reg] = f2tf32(v);
    }
    __syncthreads();

    float cst[4] = {0.f, 0.f, 0.f, 0.f};     // cell state, register-resident

    for (int t = 0; t < kT; t++) {
        const float* hread  = g_h + (size_t)(t & 1) * (kB * kU);
        float*       hwrite = g_h + (size_t)((t + 1) & 1) * (kB * kU);

        // Prefetch this thread's xz values (hide DRAM latency behind mma loop)
        const float* xzb = g_xz + ((size_t)t * kB + b0) * k4U + u_base + j0;
        float2 xz[2][4];
#pragma unroll
        for (int r = 0; r < 2; r++)
#pragma unroll
            for (int q = 0; q < 4; q++)
                xz[r][q] = __ldcg((const float2*)(xzb + (size_t)r * 8 * k4U + q * kU));

        float c[4][4];
#pragma unroll
        for (int q = 0; q < 4; q++)
#pragma unroll
            for (int k = 0; k < 4; k++) c[q][k] = 0.f;

        for (int ch = 0; ch < 8; ch++) {     // 8 chunks of K=128
            __syncthreads();
#pragma unroll
            for (int i = 0; i < 16; i++) {   // stage h chunk (2048 float4)
                int f = tid + i * NTHR;
                int row = f >> 5, kq = f & 31;
                float4 v = __ldcg((const float4*)(hread + (size_t)row * kU + ch * 128 + kq * 4));
                uint4 u;
                u.x = f2tf32(v.x); u.y = f2tf32(v.y);
                u.z = f2tf32(v.z); u.w = f2tf32(v.w);
                *(uint4*)(h_s + row * 132 + kq * 4) = u;
            }
            __syncthreads();

#pragma unroll
            for (int kc = 0; kc < 16; kc++) {
                int kcg = ch * 16 + kc;
                uint32_t a0 = h_s[(b0)     * 132 + kc * 8 + qd];
                uint32_t a1 = h_s[(b0 + 8) * 132 + kc * 8 + qd];
                uint32_t a2 = h_s[(b0)     * 132 + kc * 8 + qd + 4];
                uint32_t a3 = h_s[(b0 + 8) * 132 + kc * 8 + qd + 4];
#pragma unroll
                for (int q = 0; q < 4; q++) {
                    uint2 b = *(const uint2*)&Wr_f[((q * 128 + kcg) * 32 + l) * 2];
                    mma_tf32(c[q], a0, a1, a2, a3, b.x, b.y);
                }
            }
        }

        // Gate phase — all in registers
#pragma unroll
        for (int r = 0; r < 2; r++) {
            float2 hv;
#pragma unroll
            for (int d = 0; d < 2; d++) {
                int idx = 2 * r + d;
                float zi = c[0][idx] + (d ? xz[r][0].y : xz[r][0].x);
                float zf = c[1][idx] + (d ? xz[r][1].y : xz[r][1].x);
                float zg = c[2][idx] + (d ? xz[r][2].y : xz[r][2].x);
                float zo = c[3][idx] + (d ? xz[r][3].y : xz[r][3].x);
                float ig = 1.f / (1.f + expf(-zi));
                float fg = 1.f / (1.f + expf(-zf));
                float gg = tanhf(zg);
                float og = 1.f / (1.f + expf(-zo));
                float cv = fg * cst[idx] + ig * gg;
                cst[idx] = cv;
                float hh = og * tanhf(cv);
                if (d == 0) hv.x = hh; else hv.y = hh;
            }
            *(float2*)(hwrite + (size_t)(b0 + 8 * r) * kU + u_base + j0) = hv;
        }

        // Grid barrier (monotonic counter, reset each replay)
        __threadfence();
        __syncthreads();
        if (tid == 0) {
            atomicAdd(&g_arrive, 1u);
            unsigned target = (unsigned)(t + 1) * NCTA;
            while (*((volatile unsigned*)&g_arrive) < target) { }
        }
        __syncthreads();
    }
}

// ---------------------------------------------------------------------------
// Kernel 3: logits = h_last @ Wd + bd; softmax per row. (h in buffer 0)
// ---------------------------------------------------------------------------
__global__ __launch_bounds__(256) void dense_softmax_kernel(
    const float* __restrict__ Wd, const float* __restrict__ bd,
    float* __restrict__ out) {
    __shared__ float hrow[kU];
    __shared__ float red[256];

    const int b   = blockIdx.x;
    const int tid = threadIdx.x;
    const float* hsrc = g_h + (size_t)b * kU;    // buffer 0
    *(float4*)&hrow[tid * 4] = *(const float4*)&hsrc[tid * 4];
    __syncthreads();

    float acc[4] = {0.f, 0.f, 0.f, 0.f};
    const int j0 = tid * 4;
    const bool active = (j0 < kC);
    if (active) {
        const float* wp = Wd + j0;
#pragma unroll 4
        for (int k = 0; k < kU; k++) {
            float4 wv = *(const float4*)(wp + (size_t)k * kC);
            float  hk = hrow[k];
            acc[0] = fmaf(hk, wv.x, acc[0]);
            acc[1] = fmaf(hk, wv.y, acc[1]);
            acc[2] = fmaf(hk, wv.z, acc[2]);
            acc[3] = fmaf(hk, wv.w, acc[3]);
        }
        float4 bv = *(const float4*)&bd[j0];
        acc[0] += bv.x; acc[1] += bv.y; acc[2] += bv.z; acc[3] += bv.w;
    }

    float m = active ? fmaxf(fmaxf(acc[0], acc[1]), fmaxf(acc[2], acc[3]))
                     : -INFINITY;
    red[tid] = m;
    __syncthreads();
    for (int s = 128; s > 0; s >>= 1) {
        if (tid < s) red[tid] = fmaxf(red[tid], red[tid + s]);
        __syncthreads();
    }
    float mx = red[0];
    __syncthreads();

    float e[4] = {0.f, 0.f, 0.f, 0.f};
    float psum = 0.f;
    if (active) {
#pragma unroll
        for (int cc = 0; cc < 4; cc++) { e[cc] = expf(acc[cc] - mx); psum += e[cc]; }
    }
    red[tid] = psum;
    __syncthreads();
    for (int s = 128; s > 0; s >>= 1) {
        if (tid < s) red[tid] += red[tid + s];
        __syncthreads();
    }
    float inv = 1.f / red[0];
    if (active) {
#pragma unroll
        for (int cc = 0; cc < 4; cc++) out[(size_t)b * kC + j0 + cc] = e[cc] * inv;
    }
}

// ---------------------------------------------------------------------------
// Launch
// ---------------------------------------------------------------------------
extern "C" void kernel_launch(void* const* d_in, const int* in_sizes, int n_in,
                              void* d_out, int out_size) {
    const float* x    = (const float*)d_in[0];
    const float* Wk   = (const float*)d_in[1];
    const float* Wr   = (const float*)d_in[2];
    const float* bias = (const float*)d_in[3];
    const float* Wd   = (const float*)d_in[4];
    const float* bd   = (const float*)d_in[5];
    float* out = (float*)d_out;

    const int smem_bytes = (32768 + 64 * 132) * (int)sizeof(uint32_t);  // 164864
    cudaFuncSetAttribute(lstm_tf32, cudaFuncAttributeMaxDynamicSharedMemorySize,
                         smem_bytes);

    reset_kernel<<<64, 256>>>();
    gemm_xz_tf32<<<dim3(k4U / 128, (kB * kT) / 128), 256>>>(x, Wk, bias);
    lstm_tf32<<<NCTA, NTHR, smem_bytes>>>(Wr);
    dense_softmax_kernel<<<kB, 256>>>(Wd, bd, out);
}

// round 4
// speedup vs baseline: 2.7080x; 1.0966x over previous
#include <cuda_runtime.h>
#include <math.h>
#include <stdint.h>

// Problem constants
static constexpr int kB  = 64;      // batch
static constexpr int kT  = 1024;    // time steps
static constexpr int kF  = 512;     // input features
static constexpr int kU  = 1024;    // hidden units
static constexpr int k4U = 4096;    // 4*U (gates i,f,g,o)
static constexpr int kC  = 1000;    // classes

static constexpr int NCTA = 128;    // persistent CTAs (1/SM)
static constexpr int NTHR = 128;    // threads (4 warps)

// Scratch (device globals: allocation-free per harness rules)
__device__ float    g_xz[(size_t)kB * kT * k4U];   // [T][B][4U] layout
// h ping-pong, PERMUTED into mma A-fragment order:
//   idx(b,u) = ((u>>3)*4 + (b>>4))*128 + ((b&7)*4 + (u&3))*4
//              + ((b>>3)&1) + 2*((u&7)>>2)
__device__ float    g_h[2 * kB * kU];
__device__ unsigned g_arrive[8 * 32];              // 8 counters, 128B apart

__device__ __forceinline__ uint32_t f2tf32(float f) {
    uint32_t r;
    asm("cvt.rna.tf32.f32 %0, %1;" : "=r"(r) : "f"(f));
    return r;
}

__device__ __forceinline__ void mma_tf32(float c[4], uint32_t a0, uint32_t a1,
                                         uint32_t a2, uint32_t a3,
                                         uint32_t b0, uint32_t b1) {
    asm volatile(
        "mma.sync.aligned.m16n8k8.row.col.f32.tf32.tf32.f32 "
        "{%0,%1,%2,%3},{%4,%5,%6,%7},{%8,%9},{%0,%1,%2,%3};"
        : "+f"(c[0]), "+f"(c[1]), "+f"(c[2]), "+f"(c[3])
        : "r"(a0), "r"(a1), "r"(a2), "r"(a3), "r"(b0), "r"(b1));
}

__device__ __forceinline__ int hperm(int b, int u) {
    return ((u >> 3) * 4 + (b >> 4)) * 128 + ((b & 7) * 4 + (u & 3)) * 4 +
           ((b >> 3) & 1) + 2 * ((u & 7) >> 2);
}

// ---------------------------------------------------------------------------
// Kernel 0: reset state so every graph replay is deterministic
// ---------------------------------------------------------------------------
__global__ void reset_kernel() {
    int idx = blockIdx.x * blockDim.x + threadIdx.x;
    if (idx < 8 * 32) g_arrive[idx] = 0u;
    for (int i = idx; i < 2 * kB * kU; i += gridDim.x * blockDim.x) g_h[i] = 0.f;
}

// ---------------------------------------------------------------------------
// Kernel 1: xz = x@Wk + b  via tf32 mma.sync. Tile 128x128x16, 256 thr/8 warps.
// Output to g_xz in [T][B][4U] layout.
// ---------------------------------------------------------------------------
__global__ __launch_bounds__(256) void gemm_xz_tf32(
    const float* __restrict__ x, const float* __restrict__ Wk,
    const float* __restrict__ bias) {
    __shared__ uint32_t As[128 * 20];
    __shared__ uint32_t Bs[16 * 136];

    const int tid = threadIdx.x;
    const int w   = tid >> 5, l = tid & 31;
    const int grp = l >> 2, qd = l & 3;
    const int mw  = (w & 3) * 32;
    const int nw  = (w >> 2) * 64;
    const int n0  = blockIdx.x * 128;
    const int m0  = blockIdx.y * 128;

    float acc[2][8][4];
#pragma unroll
    for (int i = 0; i < 2; i++)
#pragma unroll
        for (int j = 0; j < 8; j++)
#pragma unroll
            for (int k = 0; k < 4; k++) acc[i][j][k] = 0.f;

    for (int k0 = 0; k0 < kF; k0 += 16) {
        __syncthreads();
#pragma unroll
        for (int i = 0; i < 2; i++) {
            int f   = tid + i * 256;
            int row = f >> 2, ks = (f & 3) * 4;
            float4 v = *(const float4*)(x + (size_t)(m0 + row) * kF + k0 + ks);
            uint32_t* p = &As[row * 20 + ks];
            p[0] = f2tf32(v.x); p[1] = f2tf32(v.y);
            p[2] = f2tf32(v.z); p[3] = f2tf32(v.w);
        }
#pragma unroll
        for (int i = 0; i < 2; i++) {
            int f  = tid + i * 256;
            int kk = f >> 5, ns = (f & 31) * 4;
            float4 v = *(const float4*)(Wk + (size_t)(k0 + kk) * k4U + n0 + ns);
            uint32_t* p = &Bs[kk * 136 + ns];
            p[0] = f2tf32(v.x); p[1] = f2tf32(v.y);
            p[2] = f2tf32(v.z); p[3] = f2tf32(v.w);
        }
        __syncthreads();

#pragma unroll
        for (int half = 0; half < 16; half += 8) {
            uint32_t a[2][4];
#pragma unroll
            for (int mt = 0; mt < 2; mt++) {
                int r = mw + mt * 16 + grp;
                a[mt][0] = As[r * 20 + half + qd];
                a[mt][1] = As[(r + 8) * 20 + half + qd];
                a[mt][2] = As[r * 20 + half + qd + 4];
                a[mt][3] = As[(r + 8) * 20 + half + qd + 4];
            }
#pragma unroll
            for (int nt = 0; nt < 8; nt++) {
                int n = nw + nt * 8 + grp;
                uint32_t b0 = Bs[(half + qd) * 136 + n];
                uint32_t b1 = Bs[(half + qd + 4) * 136 + n];
                mma_tf32(acc[0][nt], a[0][0], a[0][1], a[0][2], a[0][3], b0, b1);
                mma_tf32(acc[1][nt], a[1][0], a[1][1], a[1][2], a[1][3], b0, b1);
            }
        }
    }

#pragma unroll
    for (int nt = 0; nt < 8; nt++) {
        int col = n0 + nw + nt * 8 + 2 * qd;
        float2 bv = *(const float2*)(bias + col);
#pragma unroll
        for (int mt = 0; mt < 2; mt++) {
            int mg = m0 + mw + mt * 16 + grp;
#pragma unroll
            for (int ri = 0; ri < 2; ri++) {
                int row = mg + 8 * ri;
                int b = row >> 10;         // m = b*kT + t
                int t = row & 1023;
                float2 o;
                o.x = acc[mt][nt][2 * ri + 0] + bv.x;
                o.y = acc[mt][nt][2 * ri + 1] + bv.y;
                *(float2*)(g_xz + ((size_t)t * kB + b) * k4U + col) = o;
            }
        }
    }
}

// ---------------------------------------------------------------------------
// Kernel 2: persistent LSTM recurrence, tf32 mma.sync, SMEM-free h path.
// CTA owns units [8*cta, 8*cta+8). Wr slice staged once in fragment SMEM.
// h read directly from L2 as per-thread contiguous 16B A-fragments
// (8-deep register prefetch ring). Distributed 8-counter grid barrier.
// ---------------------------------------------------------------------------
extern __shared__ uint32_t lstm_smem_u[];

__global__ __launch_bounds__(NTHR, 1) void lstm_tf32(const float* __restrict__ Wr) {
    uint32_t* Wr_f = lstm_smem_u;            // 4*128*32*2 = 32768 u32 (128 KB)

    const int tid = threadIdx.x;
    const int w = tid >> 5, l = tid & 31;
    const int grp = l >> 2, qd = l & 3;
    const int u_base = blockIdx.x * 8;
    const int b0 = w * 16 + grp;             // thread's batch rows: b0, b0+8
    const int j0 = 2 * qd;                   // thread's units: j0, j0+1

    // Stage Wr slice into B-fragment layout (one time)
    for (int i = 0; i < 256; i++) {
        int lin = tid + i * NTHR;            // 32768 values
        int c = lin & 31, k = lin >> 5;
        int q = c >> 3, j = c & 7;
        float v = Wr[(size_t)k * k4U + q * kU + u_base + j];
        int kc = k >> 3, kr = k & 7;
        int lane = (j << 2) | (kr & 3);
        int reg  = kr >> 2;
        Wr_f[((q * 128 + kc) * 32 + lane) * 2 + reg] = f2tf32(v);
    }
    __syncthreads();

    float cst[4] = {0.f, 0.f, 0.f, 0.f};     // register-resident cell state
    const int aoff = w * 32 + l;             // uint4 index within a kcg block

    for (int t = 0; t < kT; t++) {
        const uint4* Ag = (const uint4*)(g_h + (size_t)(t & 1) * (kB * kU));
        float*     hwrt = g_h + (size_t)((t + 1) & 1) * (kB * kU);

        // xz prefetch (consumed only in gate phase; latency hidden by mma loop)
        const float* xzb = g_xz + ((size_t)t * kB + b0) * k4U + u_base + j0;
        float2 xz[2][4];
#pragma unroll
        for (int r = 0; r < 2; r++)
#pragma unroll
            for (int q = 0; q < 4; q++)
                xz[r][q] = __ldcg((const float2*)(xzb + (size_t)r * 8 * k4U + q * kU));

        float acc[4][2][4];                  // [gate][kc parity][frag]
#pragma unroll
        for (int q = 0; q < 4; q++)
#pragma unroll
            for (int p = 0; p < 2; p++)
#pragma unroll
                for (int k = 0; k < 4; k++) acc[q][p][k] = 0.f;

        // 8-deep A-fragment prefetch ring
        uint4 abuf[8];
#pragma unroll
        for (int i = 0; i < 8; i++) abuf[i] = __ldcg(Ag + i * 128 + aoff);

#pragma unroll 8
        for (int kcg = 0; kcg < 128; kcg++) {
            uint4 a = abuf[kcg & 7];
            if (kcg < 120) abuf[kcg & 7] = __ldcg(Ag + (kcg + 8) * 128 + aoff);
#pragma unroll
            for (int q = 0; q < 4; q++) {
                uint2 bv = *(const uint2*)&Wr_f[((q * 128 + kcg) * 32 + l) * 2];
                mma_tf32(acc[q][kcg & 1], a.x, a.y, a.z, a.w, bv.x, bv.y);
            }
        }

        // Gate phase — all registers. C frag: idx 2r+d => row b0+8r, unit j0+d
#pragma unroll
        for (int r = 0; r < 2; r++) {
            int b = b0 + 8 * r;
#pragma unroll
            for (int d = 0; d < 2; d++) {
                int idx = 2 * r + d;
                float zi = acc[0][0][idx] + acc[0][1][idx] + (d ? xz[r][0].y : xz[r][0].x);
                float zf = acc[1][0][idx] + acc[1][1][idx] + (d ? xz[r][1].y : xz[r][1].x);
                float zg = acc[2][0][idx] + acc[2][1][idx] + (d ? xz[r][2].y : xz[r][2].x);
                float zo = acc[3][0][idx] + acc[3][1][idx] + (d ? xz[r][3].y : xz[r][3].x);
                float ig = 1.f / (1.f + expf(-zi));
                float fg = 1.f / (1.f + expf(-zf));
                float gg = tanhf(zg);
                float og = 1.f / (1.f + expf(-zo));
                float cv = fg * cst[idx] + ig * gg;
                cst[idx] = cv;
                float hh = og * tanhf(cv);
                // pre-round to tf32 and store in permuted fragment layout
                hwrt[hperm(b, u_base + j0 + d)] = __uint_as_float(f2tf32(hh));
            }
        }

        // Distributed grid barrier (monotonic counters, reset each replay)
        __threadfence();
        __syncthreads();
        if (tid == 0) atomicAdd(&g_arrive[(blockIdx.x & 7) * 32], 1u);
        if (tid < 8) {
            volatile unsigned* p = &g_arrive[tid * 32];
            unsigned target = (unsigned)(t + 1) * 16u;
            while (*p < target) { }
        }
        __syncthreads();
        __threadfence();
    }
}

// ---------------------------------------------------------------------------
// Kernel 3: logits = h_last @ Wd + bd; softmax per row.
// h_last in buffer 0, permuted layout -> gather via hperm.
// ---------------------------------------------------------------------------
__global__ __launch_bounds__(256) void dense_softmax_kernel(
    const float* __restrict__ Wd, const float* __restrict__ bd,
    float* __restrict__ out) {
    __shared__ float hrow[kU];
    __shared__ float red[256];

    const int b   = blockIdx.x;
    const int tid = threadIdx.x;
    for (int u = tid; u < kU; u += 256) hrow[u] = g_h[hperm(b, u)];
    __syncthreads();

    float acc[4] = {0.f, 0.f, 0.f, 0.f};
    const int j0 = tid * 4;
    const bool active = (j0 < kC);
    if (active) {
        const float* wp = Wd + j0;
#pragma unroll 4
        for (int k = 0; k < kU; k++) {
            float4 wv = *(const float4*)(wp + (size_t)k * kC);
            float  hk = hrow[k];
            acc[0] = fmaf(hk, wv.x, acc[0]);
            acc[1] = fmaf(hk, wv.y, acc[1]);
            acc[2] = fmaf(hk, wv.z, acc[2]);
            acc[3] = fmaf(hk, wv.w, acc[3]);
        }
        float4 bv = *(const float4*)&bd[j0];
        acc[0] += bv.x; acc[1] += bv.y; acc[2] += bv.z; acc[3] += bv.w;
    }

    float m = active ? fmaxf(fmaxf(acc[0], acc[1]), fmaxf(acc[2], acc[3]))
                     : -INFINITY;
    red[tid] = m;
    __syncthreads();
    for (int s = 128; s > 0; s >>= 1) {
        if (tid < s) red[tid] = fmaxf(red[tid], red[tid + s]);
        __syncthreads();
    }
    float mx = red[0];
    __syncthreads();

    float e[4] = {0.f, 0.f, 0.f, 0.f};
    float psum = 0.f;
    if (active) {
#pragma unroll
        for (int cc = 0; cc < 4; cc++) { e[cc] = expf(acc[cc] - mx); psum += e[cc]; }
    }
    red[tid] = psum;
    __syncthreads();
    for (int s = 128; s > 0; s >>= 1) {
        if (tid < s) red[tid] += red[tid + s];
        __syncthreads();
    }
    float inv = 1.f / red[0];
    if (active) {
#pragma unroll
        for (int cc = 0; cc < 4; cc++) out[(size_t)b * kC + j0 + cc] = e[cc] * inv;
    }
}

// ---------------------------------------------------------------------------
// Launch
// ---------------------------------------------------------------------------
extern "C" void kernel_launch(void* const* d_in, const int* in_sizes, int n_in,
                              void* d_out, int out_size) {
    const float* x    = (const float*)d_in[0];
    const float* Wk   = (const float*)d_in[1];
    const float* Wr   = (const float*)d_in[2];
    const float* bias = (const float*)d_in[3];
    const float* Wd   = (const float*)d_in[4];
    const float* bd   = (const float*)d_in[5];
    float* out = (float*)d_out;

    const int smem_bytes = 32768 * (int)sizeof(uint32_t);   // 128 KB
    cudaFuncSetAttribute(lstm_tf32, cudaFuncAttributeMaxDynamicSharedMemorySize,
                         smem_bytes);

    reset_kernel<<<64, 256>>>();
    gemm_xz_tf32<<<dim3(k4U / 128, (kB * kT) / 128), 256>>>(x, Wk, bias);
    lstm_tf32<<<NCTA, NTHR, smem_bytes>>>(Wr);
    dense_softmax_kernel<<<kB, 256>>>(Wd, bd, out);
}

// round 5
// speedup vs baseline: 4.0214x; 1.4850x over previous
#include <cuda_runtime.h>
#include <cuda_bf16.h>
#include <math.h>
#include <stdint.h>

// Problem constants
static constexpr int kB  = 64;      // batch
static constexpr int kT  = 1024;    // time steps
static constexpr int kF  = 512;     // input features
static constexpr int kU  = 1024;    // hidden units
static constexpr int k4U = 4096;    // 4*U (gates i,f,g,o)
static constexpr int kC  = 1000;    // classes

static constexpr int NCTA = 128;    // persistent CTAs (1/SM)
static constexpr int NTHR = 128;    // threads (4 warps)

// Scratch (device globals: allocation-free per harness rules)
__device__ float    g_xz[(size_t)kB * kT * k4U];   // [T][B][4U] fp32
// h ping-pong, bf16, permuted into m16n8k16 A-fragment order.
// u32 index (per 32768-u32 buffer):
//   ((u>>4)*128 + (b>>4)*32 + (b&7)*4 + ((u&7)>>1))*4 + 2*((u>>3)&1) + ((b>>3)&1)
// within u32: low bf16 = even u, high bf16 = odd u.
__device__ uint32_t g_h[2 * 32768];
__device__ unsigned g_arrive[8 * 32];              // 8 counters, 128B apart

__device__ __forceinline__ uint32_t pack_bf16(float lo, float hi) {
    uint32_t r;
    asm("cvt.rn.bf16x2.f32 %0, %1, %2;" : "=r"(r) : "f"(hi), "f"(lo));
    return r;
}

__device__ __forceinline__ float tanh_fast(float x) {
    float r;
    asm("tanh.approx.f32 %0, %1;" : "=f"(r) : "f"(x));
    return r;
}
__device__ __forceinline__ float sigmoid_fast(float x) {
    return 1.f / (1.f + __expf(-x));
}

__device__ __forceinline__ void mma_bf16(float c[4], uint32_t a0, uint32_t a1,
                                         uint32_t a2, uint32_t a3,
                                         uint32_t b0, uint32_t b1) {
    asm volatile(
        "mma.sync.aligned.m16n8k16.row.col.f32.bf16.bf16.f32 "
        "{%0,%1,%2,%3},{%4,%5,%6,%7},{%8,%9},{%0,%1,%2,%3};"
        : "+f"(c[0]), "+f"(c[1]), "+f"(c[2]), "+f"(c[3])
        : "r"(a0), "r"(a1), "r"(a2), "r"(a3), "r"(b0), "r"(b1));
}

// ---------------------------------------------------------------------------
// Kernel 0: reset state so every graph replay is deterministic
// ---------------------------------------------------------------------------
__global__ void reset_kernel() {
    int idx = blockIdx.x * blockDim.x + threadIdx.x;
    if (idx < 8 * 32) g_arrive[idx] = 0u;
    for (int i = idx; i < 2 * 32768; i += gridDim.x * blockDim.x) g_h[i] = 0u;
}

// ---------------------------------------------------------------------------
// Kernel 1: xz = x@Wk + b via bf16 m16n8k16 mma. Tile 128x128x16, 256 thr,
// 8 warps, warp tile 32x64. Output g_xz in [T][B][4U] fp32 layout.
// As[row][kp] u32 bf16x2 stride 12 (conflict-free A-frag LDS),
// Bs[kp][n]   u32 bf16x2 stride 136 (conflict-free B-frag LDS).
// ---------------------------------------------------------------------------
__global__ __launch_bounds__(256) void gemm_xz_bf16(
    const float* __restrict__ x, const float* __restrict__ Wk,
    const float* __restrict__ bias) {
    __shared__ uint32_t As[128 * 12];
    __shared__ uint32_t Bs[8 * 136];

    const int tid = threadIdx.x;
    const int w   = tid >> 5, l = tid & 31;
    const int grp = l >> 2, qd = l & 3;
    const int mw  = (w & 3) * 32;
    const int nw  = (w >> 2) * 64;
    const int n0  = blockIdx.x * 128;
    const int m0  = blockIdx.y * 128;

    float acc[2][8][4];
#pragma unroll
    for (int i = 0; i < 2; i++)
#pragma unroll
        for (int j = 0; j < 8; j++)
#pragma unroll
            for (int k = 0; k < 4; k++) acc[i][j][k] = 0.f;

    for (int k0 = 0; k0 < kF; k0 += 16) {
        __syncthreads();
        // stage A: x tile 128x16 -> bf16 pairs (1024 u32)
#pragma unroll
        for (int i = 0; i < 4; i++) {
            int f = tid + i * 256;
            int row = f >> 3, kp = f & 7;
            float2 v = *(const float2*)(x + (size_t)(m0 + row) * kF + k0 + 2 * kp);
            As[row * 12 + kp] = pack_bf16(v.x, v.y);
        }
        // stage B: Wk tile 16x128 -> bf16 pairs along k (1024 u32)
#pragma unroll
        for (int i = 0; i < 4; i++) {
            int f = tid + i * 256;
            int kp = f >> 7, n = f & 127;
            float v0 = Wk[(size_t)(k0 + 2 * kp) * k4U + n0 + n];
            float v1 = Wk[(size_t)(k0 + 2 * kp + 1) * k4U + n0 + n];
            Bs[kp * 136 + n] = pack_bf16(v0, v1);
        }
        __syncthreads();

        uint32_t a[2][4];
#pragma unroll
        for (int mt = 0; mt < 2; mt++) {
            int r = mw + mt * 16 + grp;
            a[mt][0] = As[r * 12 + qd];
            a[mt][1] = As[(r + 8) * 12 + qd];
            a[mt][2] = As[r * 12 + qd + 4];
            a[mt][3] = As[(r + 8) * 12 + qd + 4];
        }
#pragma unroll
        for (int nt = 0; nt < 8; nt++) {
            int n = nw + nt * 8 + grp;
            uint32_t b0 = Bs[qd * 136 + n];
            uint32_t b1 = Bs[(qd + 4) * 136 + n];
            mma_bf16(acc[0][nt], a[0][0], a[0][1], a[0][2], a[0][3], b0, b1);
            mma_bf16(acc[1][nt], a[1][0], a[1][1], a[1][2], a[1][3], b0, b1);
        }
    }

#pragma unroll
    for (int nt = 0; nt < 8; nt++) {
        int col = n0 + nw + nt * 8 + 2 * qd;
        float2 bv = *(const float2*)(bias + col);
#pragma unroll
        for (int mt = 0; mt < 2; mt++) {
            int mg = m0 + mw + mt * 16 + grp;
#pragma unroll
            for (int ri = 0; ri < 2; ri++) {
                int row = mg + 8 * ri;
                int b = row >> 10;         // m = b*kT + t
                int t = row & 1023;
                float2 o;
                o.x = acc[mt][nt][2 * ri + 0] + bv.x;
                o.y = acc[mt][nt][2 * ri + 1] + bv.y;
                *(float2*)(g_xz + ((size_t)t * kB + b) * k4U + col) = o;
            }
        }
    }
}

// ---------------------------------------------------------------------------
// Kernel 2: persistent LSTM recurrence, bf16 m16n8k16 mma, SMEM-free h path.
// CTA owns units [8*cta, 8*cta+8). Wr slice staged once in B-frag SMEM (64KB).
// h read from L2 as one contiguous uint4 A-fragment per thread per 16-K block
// (8-deep register prefetch ring). Distributed 8-counter grid barrier.
// ---------------------------------------------------------------------------
extern __shared__ uint32_t lstm_smem_u[];

__global__ __launch_bounds__(NTHR, 1) void lstm_bf16(const float* __restrict__ Wr) {
    uint32_t* Wr_f = lstm_smem_u;            // 4*64*32*2 = 16384 u32 (64 KB)

    const int tid = threadIdx.x;
    const int w = tid >> 5, l = tid & 31;
    const int grp = l >> 2, qd = l & 3;
    const int u_base = blockIdx.x * 8;
    const int b0 = w * 16 + grp;             // thread's batch rows: b0, b0+8
    const int j0 = 2 * qd;                   // thread's units: j0, j0+1

    // Writer constants: h element (b, u_base + 2qd + {0,1})
    const int kcg_w = blockIdx.x >> 1;       // u_base>>4
    const int hi_w  = blockIdx.x & 1;        // (u_base>>3)&1

    // Stage Wr slice into bf16 B-fragment layout (one time, 16384 u32)
    for (int i = 0; i < 128; i++) {
        int lin = tid + i * NTHR;
        int reg = lin & 1;
        int ll  = (lin >> 1) & 31;
        int kcg = (lin >> 6) & 63;
        int q   = (lin >> 12) & 3;
        int lg = ll >> 2, lq = ll & 3;
        int k  = kcg * 16 + 2 * lq + 8 * reg;
        int col = q * kU + u_base + lg;
        float v0 = Wr[(size_t)k * k4U + col];
        float v1 = Wr[(size_t)(k + 1) * k4U + col];
        Wr_f[((q * 64 + kcg) * 32 + ll) * 2 + reg] = pack_bf16(v0, v1);
    }
    __syncthreads();

    float cst[4] = {0.f, 0.f, 0.f, 0.f};     // register-resident cell state

    for (int t = 0; t < kT; t++) {
        const uint4* Ag = (const uint4*)(g_h + (size_t)(t & 1) * 32768);
        uint32_t*  hwrt = g_h + (size_t)((t + 1) & 1) * 32768;

        // xz prefetch (fp32; consumed in gate phase)
        const float* xzb = g_xz + ((size_t)t * kB + b0) * k4U + u_base + j0;
        float2 xz[2][4];
#pragma unroll
        for (int r = 0; r < 2; r++)
#pragma unroll
            for (int q = 0; q < 4; q++)
                xz[r][q] = __ldcg((const float2*)(xzb + (size_t)r * 8 * k4U + q * kU));

        float acc[4][2][4];                  // [gate][kcg parity][frag]
#pragma unroll
        for (int q = 0; q < 4; q++)
#pragma unroll
            for (int p = 0; p < 2; p++)
#pragma unroll
                for (int k = 0; k < 4; k++) acc[q][p][k] = 0.f;

        // 8-deep A-fragment prefetch ring: uint4 idx = kcg*128 + tid
        uint4 abuf[8];
#pragma unroll
        for (int i = 0; i < 8; i++) abuf[i] = __ldcg(Ag + i * 128 + tid);

#pragma unroll 8
        for (int kcg = 0; kcg < 64; kcg++) {
            uint4 a = abuf[kcg & 7];
            if (kcg < 56) abuf[kcg & 7] = __ldcg(Ag + (kcg + 8) * 128 + tid);
#pragma unroll
            for (int q = 0; q < 4; q++) {
                uint2 bv = *(const uint2*)&Wr_f[((q * 64 + kcg) * 32 + l) * 2];
                mma_bf16(acc[q][kcg & 1], a.x, a.y, a.z, a.w, bv.x, bv.y);
            }
        }

        // Gate phase — registers only. C frag idx 2r+d: row b0+8r, unit j0+d.
#pragma unroll
        for (int r = 0; r < 2; r++) {
            float hv[2];
#pragma unroll
            for (int d = 0; d < 2; d++) {
                int idx = 2 * r + d;
                float zi = acc[0][0][idx] + acc[0][1][idx] + (d ? xz[r][0].y : xz[r][0].x);
                float zf = acc[1][0][idx] + acc[1][1][idx] + (d ? xz[r][1].y : xz[r][1].x);
                float zg = acc[2][0][idx] + acc[2][1][idx] + (d ? xz[r][2].y : xz[r][2].x);
                float zo = acc[3][0][idx] + acc[3][1][idx] + (d ? xz[r][3].y : xz[r][3].x);
                float ig = sigmoid_fast(zi);
                float fg = sigmoid_fast(zf);
                float gg = tanh_fast(zg);
                float og = sigmoid_fast(zo);
                float cv = fg * cst[idx] + ig * gg;
                cst[idx] = cv;
                hv[d] = og * tanh_fast(cv);
            }
            // one bf16x2 store: units (j0, j0+1) of row b0+8r
            hwrt[(kcg_w * 128 + tid) * 4 + 2 * hi_w + r] = pack_bf16(hv[0], hv[1]);
        }

        // Distributed grid barrier (monotonic counters, reset each replay)
        __threadfence();
        __syncthreads();
        if (tid == 0) atomicAdd(&g_arrive[(blockIdx.x & 7) * 32], 1u);
        if (tid < 8) {
            volatile unsigned* p = &g_arrive[tid * 32];
            unsigned target = (unsigned)(t + 1) * 16u;
            while (*p < target) { }
        }
        __syncthreads();
        __threadfence();
    }
}

// ---------------------------------------------------------------------------
// Kernel 3: logits = h_last @ Wd + bd; softmax per row.
// h_last in buffer 0 (bf16, permuted) -> gather + widen.
// ---------------------------------------------------------------------------
__device__ __forceinline__ float h_read_b0(int b, int u) {
    uint32_t v = g_h[((u >> 4) * 128 + (b >> 4) * 32 + (b & 7) * 4 + ((u & 7) >> 1)) * 4
                     + 2 * ((u >> 3) & 1) + ((b >> 3) & 1)];
    return __uint_as_float((u & 1) ? (v & 0xffff0000u) : (v << 16));
}

__global__ __launch_bounds__(256) void dense_softmax_kernel(
    const float* __restrict__ Wd, const float* __restrict__ bd,
    float* __restrict__ out) {
    __shared__ float hrow[kU];
    __shared__ float red[256];

    const int b   = blockIdx.x;
    const int tid = threadIdx.x;
    for (int u = tid; u < kU; u += 256) hrow[u] = h_read_b0(b, u);
    __syncthreads();

    float acc[4] = {0.f, 0.f, 0.f, 0.f};
    const int j0 = tid * 4;
    const bool active = (j0 < kC);
    if (active) {
        const float* wp = Wd + j0;
#pragma unroll 4
        for (int k = 0; k < kU; k++) {
            float4 wv = *(const float4*)(wp + (size_t)k * kC);
            float  hk = hrow[k];
            acc[0] = fmaf(hk, wv.x, acc[0]);
            acc[1] = fmaf(hk, wv.y, acc[1]);
            acc[2] = fmaf(hk, wv.z, acc[2]);
            acc[3] = fmaf(hk, wv.w, acc[3]);
        }
        float4 bv = *(const float4*)&bd[j0];
        acc[0] += bv.x; acc[1] += bv.y; acc[2] += bv.z; acc[3] += bv.w;
    }

    float m = active ? fmaxf(fmaxf(acc[0], acc[1]), fmaxf(acc[2], acc[3]))
                     : -INFINITY;
    red[tid] = m;
    __syncthreads();
    for (int s = 128; s > 0; s >>= 1) {
        if (tid < s) red[tid] = fmaxf(red[tid], red[tid + s]);
        __syncthreads();
    }
    float mx = red[0];
    __syncthreads();

    float e[4] = {0.f, 0.f, 0.f, 0.f};
    float psum = 0.f;
    if (active) {
#pragma unroll
        for (int cc = 0; cc < 4; cc++) { e[cc] = expf(acc[cc] - mx); psum += e[cc]; }
    }
    red[tid] = psum;
    __syncthreads();
    for (int s = 128; s > 0; s >>= 1) {
        if (tid < s) red[tid] += red[tid + s];
        __syncthreads();
    }
    float inv = 1.f / red[0];
    if (active) {
#pragma unroll
        for (int cc = 0; cc < 4; cc++) out[(size_t)b * kC + j0 + cc] = e[cc] * inv;
    }
}

// ---------------------------------------------------------------------------
// Launch
// ---------------------------------------------------------------------------
extern "C" void kernel_launch(void* const* d_in, const int* in_sizes, int n_in,
                              void* d_out, int out_size) {
    const float* x    = (const float*)d_in[0];
    const float* Wk   = (const float*)d_in[1];
    const float* Wr   = (const float*)d_in[2];
    const float* bias = (const float*)d_in[3];
    const float* Wd   = (const float*)d_in[4];
    const float* bd   = (const float*)d_in[5];
    float* out = (float*)d_out;

    const int smem_bytes = 16384 * (int)sizeof(uint32_t);   // 64 KB
    cudaFuncSetAttribute(lstm_bf16, cudaFuncAttributeMaxDynamicSharedMemorySize,
                         smem_bytes);

    reset_kernel<<<64, 256>>>();
    gemm_xz_bf16<<<dim3(k4U / 128, (kB * kT) / 128), 256>>>(x, Wk, bias);
    lstm_bf16<<<NCTA, NTHR, smem_bytes>>>(Wr);
    dense_softmax_kernel<<<kB, 256>>>(Wd, bd, out);
}

// round 7
// speedup vs baseline: 4.1773x; 1.0388x over previous
#include <cuda_runtime.h>
#include <cuda_bf16.h>
#include <math.h>
#include <stdint.h>

// Problem constants
static constexpr int kB  = 64;      // batch
static constexpr int kT  = 1024;    // time steps
static constexpr int kF  = 512;     // input features
static constexpr int kU  = 1024;    // hidden units
static constexpr int k4U = 4096;    // 4*U (gates i,f,g,o)
static constexpr int kC  = 1000;    // classes

static constexpr int NCTA = 128;    // persistent CTAs (1/SM)
static constexpr int NTHR = 128;    // threads (4 warps)

// Scratch (device globals: allocation-free per harness rules)
__device__ float    g_xz[(size_t)kB * kT * k4U];   // [T][B][4U] fp32
// h ping-pong, bf16, permuted into m16n8k16 A-fragment order.
// u32 index (per 32768-u32 buffer):
//   ((u>>4)*128 + (b>>4)*32 + (b&7)*4 + ((u&7)>>1))*4 + 2*((u>>3)&1) + ((b>>3)&1)
// within u32: low bf16 = even u, high bf16 = odd u.
__device__ uint32_t g_h[2 * 32768];
// Per-group monotonic step-completion counters. Group g = CTAs [16g,16g+16)
// = h units [128g, 128g+128) = A-fragment chunks kcg in [8g, 8g+8).
__device__ unsigned g_cnt[8 * 32];                 // 128B apart

__device__ __forceinline__ uint32_t pack_bf16(float lo, float hi) {
    uint32_t r;
    asm("cvt.rn.bf16x2.f32 %0, %1, %2;" : "=r"(r) : "f"(hi), "f"(lo));
    return r;
}

__device__ __forceinline__ float tanh_fast(float x) {
    float r;
    asm("tanh.approx.f32 %0, %1;" : "=f"(r) : "f"(x));
    return r;
}
__device__ __forceinline__ float sigmoid_fast(float x) {
    return 1.f / (1.f + __expf(-x));
}

__device__ __forceinline__ void mma_bf16(float c[4], uint32_t a0, uint32_t a1,
                                         uint32_t a2, uint32_t a3,
                                         uint32_t b0, uint32_t b1) {
    asm volatile(
        "mma.sync.aligned.m16n8k16.row.col.f32.bf16.bf16.f32 "
        "{%0,%1,%2,%3},{%4,%5,%6,%7},{%8,%9},{%0,%1,%2,%3};"
        : "+f"(c[0]), "+f"(c[1]), "+f"(c[2]), "+f"(c[3])
        : "r"(a0), "r"(a1), "r"(a2), "r"(a3), "r"(b0), "r"(b1));
}

// Warp-cooperative group-counter poll. Lanes 0-7 each own one group counter;
// returns a ballot mask whose bits 0-7 indicate groups with cnt >= tgt.
// Acquire load orders subsequent h reads; consumer h loads are additionally
// control-dependent on the returned mask.
__device__ __forceinline__ unsigned poll_groups(int lane, unsigned tgt,
                                                unsigned rdy) {
    unsigned ok = 1u;
    if (lane < 8 && !((rdy >> lane) & 1u)) {
        unsigned v;
        asm volatile("ld.acquire.gpu.u32 %0, [%1];"
                     : "=r"(v) : "l"(&g_cnt[lane * 32]) : "memory");
        ok = (v >= tgt) ? 1u : 0u;
    }
    return __ballot_sync(0xffffffffu, ok != 0u);
}

// ---------------------------------------------------------------------------
// Kernel 0: reset state so every graph replay is deterministic
// ---------------------------------------------------------------------------
__global__ void reset_kernel() {
    int idx = blockIdx.x * blockDim.x + threadIdx.x;
    if (idx < 8 * 32) g_cnt[idx] = 0u;
    for (int i = idx; i < 2 * 32768; i += gridDim.x * blockDim.x) g_h[i] = 0u;
}

// ---------------------------------------------------------------------------
// Kernel 1: xz = x@Wk + b via bf16 m16n8k16 mma. Tile 128x128x16, 256 thr,
// 8 warps, warp tile 32x64. Output g_xz in [T][B][4U] fp32 layout.
// ---------------------------------------------------------------------------
__global__ __launch_bounds__(256) void gemm_xz_bf16(
    const float* __restrict__ x, const float* __restrict__ Wk,
    const float* __restrict__ bias) {
    __shared__ uint32_t As[128 * 12];
    __shared__ uint32_t Bs[8 * 136];

    const int tid = threadIdx.x;
    const int w   = tid >> 5, l = tid & 31;
    const int grp = l >> 2, qd = l & 3;
    const int mw  = (w & 3) * 32;
    const int nw  = (w >> 2) * 64;
    const int n0  = blockIdx.x * 128;
    const int m0  = blockIdx.y * 128;

    float acc[2][8][4];
#pragma unroll
    for (int i = 0; i < 2; i++)
#pragma unroll
        for (int j = 0; j < 8; j++)
#pragma unroll
            for (int k = 0; k < 4; k++) acc[i][j][k] = 0.f;

    for (int k0 = 0; k0 < kF; k0 += 16) {
        __syncthreads();
        // stage A: x tile 128x16 -> bf16 pairs (1024 u32)
#pragma unroll
        for (int i = 0; i < 4; i++) {
            int f = tid + i * 256;
            int row = f >> 3, kp = f & 7;
            float2 v = *(const float2*)(x + (size_t)(m0 + row) * kF + k0 + 2 * kp);
            As[row * 12 + kp] = pack_bf16(v.x, v.y);
        }
        // stage B: Wk tile 16x128 -> bf16 pairs along k (1024 u32)
#pragma unroll
        for (int i = 0; i < 4; i++) {
            int f = tid + i * 256;
            int kp = f >> 7, n = f & 127;
            float v0 = Wk[(size_t)(k0 + 2 * kp) * k4U + n0 + n];
            float v1 = Wk[(size_t)(k0 + 2 * kp + 1) * k4U + n0 + n];
            Bs[kp * 136 + n] = pack_bf16(v0, v1);
        }
        __syncthreads();

        uint32_t a[2][4];
#pragma unroll
        for (int mt = 0; mt < 2; mt++) {
            int r = mw + mt * 16 + grp;
            a[mt][0] = As[r * 12 + qd];
            a[mt][1] = As[(r + 8) * 12 + qd];
            a[mt][2] = As[r * 12 + qd + 4];
            a[mt][3] = As[(r + 8) * 12 + qd + 4];
        }
#pragma unroll
        for (int nt = 0; nt < 8; nt++) {
            int n = nw + nt * 8 + grp;
            uint32_t b0 = Bs[qd * 136 + n];
            uint32_t b1 = Bs[(qd + 4) * 136 + n];
            mma_bf16(acc[0][nt], a[0][0], a[0][1], a[0][2], a[0][3], b0, b1);
            mma_bf16(acc[1][nt], a[1][0], a[1][1], a[1][2], a[1][3], b0, b1);
        }
    }

#pragma unroll
    for (int nt = 0; nt < 8; nt++) {
        int col = n0 + nw + nt * 8 + 2 * qd;
        float2 bv = *(const float2*)(bias + col);
#pragma unroll
        for (int mt = 0; mt < 2; mt++) {
            int mg = m0 + mw + mt * 16 + grp;
#pragma unroll
            for (int ri = 0; ri < 2; ri++) {
                int row = mg + 8 * ri;
                int b = row >> 10;         // m = b*kT + t
                int t = row & 1023;
                float2 o;
                o.x = acc[mt][nt][2 * ri + 0] + bv.x;
                o.y = acc[mt][nt][2 * ri + 1] + bv.y;
                *(float2*)(g_xz + ((size_t)t * kB + b) * k4U + col) = o;
            }
        }
    }
}

// ---------------------------------------------------------------------------
// Kernel 2: persistent LSTM recurrence, bf16 m16n8k16 mma, SMEM-free h path.
// CTA owns units [8*cta, 8*cta+8). Wr slice staged once in B-frag SMEM (64KB).
// h read from L2 as one contiguous uint4 A-fragment per thread per 16-K block
// (8-deep register prefetch ring). NO full grid barrier: per-group monotonic
// counters, waited per 8-kcg chunk just-in-time (skew pipelined over chunks).
// 2-buffer ping-pong WAR safety: a CTA writing h(t+2) has passed all step-
// (t+1) waits => all CTAs posted h(t+1) => all finished reading h(t).
// ---------------------------------------------------------------------------
extern __shared__ uint32_t lstm_smem_u[];

__global__ __launch_bounds__(NTHR, 1) void lstm_bf16(const float* __restrict__ Wr) {
    uint32_t* Wr_f = lstm_smem_u;            // 4*64*32*2 = 16384 u32 (64 KB)

    const int tid = threadIdx.x;
    const int w = tid >> 5, l = tid & 31;
    const int grp = l >> 2, qd = l & 3;
    const int u_base = blockIdx.x * 8;
    const int b0 = w * 16 + grp;             // thread's batch rows: b0, b0+8
    const int j0 = 2 * qd;                   // thread's units: j0, j0+1

    // Writer constants: h element (b, u_base + 2qd + {0,1})
    const int kcg_w = blockIdx.x >> 1;       // u_base>>4
    const int hi_w  = blockIdx.x & 1;        // (u_base>>3)&1
    const int my_group = blockIdx.x >> 4;

    // Stage Wr slice into bf16 B-fragment layout (one time, 16384 u32)
    for (int i = 0; i < 128; i++) {
        int lin = tid + i * NTHR;
        int reg = lin & 1;
        int ll  = (lin >> 1) & 31;
        int kcg = (lin >> 6) & 63;
        int q   = (lin >> 12) & 3;
        int lg = ll >> 2, lq = ll & 3;
        int k  = kcg * 16 + 2 * lq + 8 * reg;
        int col = q * kU + u_base + lg;
        float v0 = Wr[(size_t)k * k4U + col];
        float v1 = Wr[(size_t)(k + 1) * k4U + col];
        Wr_f[((q * 64 + kcg) * 32 + ll) * 2 + reg] = pack_bf16(v0, v1);
    }
    __syncthreads();

    float cst[4] = {0.f, 0.f, 0.f, 0.f};     // register-resident cell state

    for (int t = 0; t < kT; t++) {
        const uint4* Ag = (const uint4*)(g_h + (size_t)(t & 1) * 32768);
        uint32_t*  hwrt = g_h + (size_t)((t + 1) & 1) * 32768;

        // xz prefetch first (independent of counters; hides L2 latency
        // behind the polling + mma loop)
        const float* xzb = g_xz + ((size_t)t * kB + b0) * k4U + u_base + j0;
        float2 xz[2][4];
#pragma unroll
        for (int r = 0; r < 2; r++)
#pragma unroll
            for (int q = 0; q < 4; q++)
                xz[r][q] = __ldcg((const float2*)(xzb + (size_t)r * 8 * k4U + q * kU));

        // Group-ready mask for this step (t=0 reads the zeroed initial buffer)
        unsigned tgt = 16u * (unsigned)t;
        unsigned rdy = (t == 0) ? 0xffffffffu : 0u;
        while (!(rdy & 1u)) rdy = poll_groups(l, tgt, rdy);

        float acc[4][2][4];                  // [gate][kcg parity][frag]
#pragma unroll
        for (int q = 0; q < 4; q++)
#pragma unroll
            for (int p = 0; p < 2; p++)
#pragma unroll
                for (int k = 0; k < 4; k++) acc[q][p][k] = 0.f;

        // Ring fill: kcg 0..7 (exactly group 0's fragments)
        uint4 abuf[8];
#pragma unroll
        for (int i = 0; i < 8; i++) abuf[i] = __ldcg(Ag + i * 128 + tid);

        for (int ch = 0; ch < 8; ch++) {
            // Before prefetching group ch+1's fragments, ensure it is posted.
            if (ch < 7)
                while (!((rdy >> (ch + 1)) & 1u))
                    rdy = poll_groups(l, tgt, rdy);
#pragma unroll
            for (int k8 = 0; k8 < 8; k8++) {
                int kcg = ch * 8 + k8;
                uint4 a = abuf[k8];
                if (kcg < 56) abuf[k8] = __ldcg(Ag + (kcg + 8) * 128 + tid);
#pragma unroll
                for (int q = 0; q < 4; q++) {
                    uint2 bv = *(const uint2*)&Wr_f[((q * 64 + kcg) * 32 + l) * 2];
                    mma_bf16(acc[q][kcg & 1], a.x, a.y, a.z, a.w, bv.x, bv.y);
                }
            }
        }

        // Gate phase — registers only. C frag idx 2r+d: row b0+8r, unit j0+d.
#pragma unroll
        for (int r = 0; r < 2; r++) {
            float hv[2];
#pragma unroll
            for (int d = 0; d < 2; d++) {
                int idx = 2 * r + d;
                float zi = acc[0][0][idx] + acc[0][1][idx] + (d ? xz[r][0].y : xz[r][0].x);
                float zf = acc[1][0][idx] + acc[1][1][idx] + (d ? xz[r][1].y : xz[r][1].x);
                float zg = acc[2][0][idx] + acc[2][1][idx] + (d ? xz[r][2].y : xz[r][2].x);
                float zo = acc[3][0][idx] + acc[3][1][idx] + (d ? xz[r][3].y : xz[r][3].x);
                float ig = sigmoid_fast(zi);
                float fg = sigmoid_fast(zf);
                float gg = tanh_fast(zg);
                float og = sigmoid_fast(zo);
                float cv = fg * cst[idx] + ig * gg;
                cst[idx] = cv;
                hv[d] = og * tanh_fast(cv);
            }
            // one bf16x2 store: units (j0, j0+1) of row b0+8r
            hwrt[(kcg_w * 128 + tid) * 4 + 2 * hi_w + r] = pack_bf16(hv[0], hv[1]);
        }

        // Publish: all warps' stores done -> one release arrival per CTA.
        __threadfence();
        __syncthreads();
        if (tid == 0) atomicAdd(&g_cnt[my_group * 32], 1u);
    }
}

// ---------------------------------------------------------------------------
// Kernel 3: logits = h_last @ Wd + bd; softmax per row.
// h_last in buffer 0 (bf16, permuted) -> gather + widen.
// ---------------------------------------------------------------------------
__device__ __forceinline__ float h_read_b0(int b, int u) {
    uint32_t v = g_h[((u >> 4) * 128 + (b >> 4) * 32 + (b & 7) * 4 + ((u & 7) >> 1)) * 4
                     + 2 * ((u >> 3) & 1) + ((b >> 3) & 1)];
    return __uint_as_float((u & 1) ? (v & 0xffff0000u) : (v << 16));
}

__global__ __launch_bounds__(256) void dense_softmax_kernel(
    const float* __restrict__ Wd, const float* __restrict__ bd,
    float* __restrict__ out) {
    __shared__ float hrow[kU];
    __shared__ float red[256];

    const int b   = blockIdx.x;
    const int tid = threadIdx.x;
    for (int u = tid; u < kU; u += 256) hrow[u] = h_read_b0(b, u);
    __syncthreads();

    float acc[4] = {0.f, 0.f, 0.f, 0.f};
    const int j0 = tid * 4;
    const bool active = (j0 < kC);
    if (active) {
        const float* wp = Wd + j0;
#pragma unroll 4
        for (int k = 0; k < kU; k++) {
            float4 wv = *(const float4*)(wp + (size_t)k * kC);
            float  hk = hrow[k];
            acc[0] = fmaf(hk, wv.x, acc[0]);
            acc[1] = fmaf(hk, wv.y, acc[1]);
            acc[2] = fmaf(hk, wv.z, acc[2]);
            acc[3] = fmaf(hk, wv.w, acc[3]);
        }
        float4 bv = *(const float4*)&bd[j0];
        acc[0] += bv.x; acc[1] += bv.y; acc[2] += bv.z; acc[3] += bv.w;
    }

    float m = active ? fmaxf(fmaxf(acc[0], acc[1]), fmaxf(acc[2], acc[3]))
                     : -INFINITY;
    red[tid] = m;
    __syncthreads();
    for (int s = 128; s > 0; s >>= 1) {
        if (tid < s) red[tid] = fmaxf(red[tid], red[tid + s]);
        __syncthreads();
    }
    float mx = red[0];
    __syncthreads();

    float e[4] = {0.f, 0.f, 0.f, 0.f};
    float psum = 0.f;
    if (active) {
#pragma unroll
        for (int cc = 0; cc < 4; cc++) { e[cc] = expf(acc[cc] - mx); psum += e[cc]; }
    }
    red[tid] = psum;
    __syncthreads();
    for (int s = 128; s > 0; s >>= 1) {
        if (tid < s) red[tid] += red[tid + s];
        __syncthreads();
    }
    float inv = 1.f / red[0];
    if (active) {
#pragma unroll
        for (int cc = 0; cc < 4; cc++) out[(size_t)b * kC + j0 + cc] = e[cc] * inv;
    }
}

// ---------------------------------------------------------------------------
// Launch
// ---------------------------------------------------------------------------
extern "C" void kernel_launch(void* const* d_in, const int* in_sizes, int n_in,
                              void* d_out, int out_size) {
    const float* x    = (const float*)d_in[0];
    const float* Wk   = (const float*)d_in[1];
    const float* Wr   = (const float*)d_in[2];
    const float* bias = (const float*)d_in[3];
    const float* Wd   = (const float*)d_in[4];
    const float* bd   = (const float*)d_in[5];
    float* out = (float*)d_out;

    const int smem_bytes = 16384 * (int)sizeof(uint32_t);   // 64 KB
    cudaFuncSetAttribute(lstm_bf16, cudaFuncAttributeMaxDynamicSharedMemorySize,
                         smem_bytes);

    reset_kernel<<<64, 256>>>();
    gemm_xz_bf16<<<dim3(k4U / 128, (kB * kT) / 128), 256>>>(x, Wk, bias);
    lstm_bf16<<<NCTA, NTHR, smem_bytes>>>(Wr);
    dense_softmax_kernel<<<kB, 256>>>(Wd, bd, out);
}

// round 8
// speedup vs baseline: 5.3278x; 1.2754x over previous
#include <cuda_runtime.h>
#include <cuda_bf16.h>
#include <math.h>
#include <stdint.h>

// Problem constants
static constexpr int kB  = 64;      // batch
static constexpr int kT  = 1024;    // time steps
static constexpr int kF  = 512;     // input features
static constexpr int kU  = 1024;    // hidden units
static constexpr int k4U = 4096;    // 4*U
static constexpr int kC  = 1000;    // classes

static constexpr int NCTA = 128;    // persistent CTAs (1/SM)
static constexpr int NTHR = 256;    // 8 warps: 0-3 consumers (LSTM), 4-7 producers (xz)

// SMEM layout (u32 units within dynamic smem)
static constexpr int OFF_WRF   = 0;        // Wr fragments: 16384 u32 (64 KB)
static constexpr int OFF_WKF   = 16384;    // Wk fragments: 4096 uint2 = 8192 u32 (32 KB)
static constexpr int OFF_RING  = 24576;    // xz ring: 4 stages x 64 x 34 fp32 = 8704 u32
static constexpr int OFF_BIAS  = 33280;    // 32 fp32
static constexpr int OFF_FLAGS = 33312;    // prod_done[4], cons_done[4]
static constexpr int SMEM_U32  = 33320;    // 133280 bytes

// Scratch (device globals: allocation-free per harness rules)
// x permuted to bf16 A-fragment order: idx(t,kcg,mt,lane) = t*4096 + kcg*128 + mt*32 + lane
__device__ uint4    g_xf[(size_t)kT * 4096];       // 67 MB
// h ping-pong, bf16, permuted into m16n8k16 A-fragment order (see R5 comment)
__device__ uint32_t g_h[2 * 32768];
// Per-group monotonic step counters. Group g = CTAs [16g,16g+16) = kcg [8g,8g+8).
__device__ unsigned g_cnt[8 * 32];

__device__ __forceinline__ uint32_t pack_bf16(float lo, float hi) {
    uint32_t r;
    asm("cvt.rn.bf16x2.f32 %0, %1, %2;" : "=r"(r) : "f"(hi), "f"(lo));
    return r;
}
__device__ __forceinline__ float tanh_fast(float x) {
    float r;
    asm("tanh.approx.f32 %0, %1;" : "=f"(r) : "f"(x));
    return r;
}
__device__ __forceinline__ float sigmoid_fast(float x) {
    return 1.f / (1.f + __expf(-x));
}
__device__ __forceinline__ void mma_bf16(float c[4], uint32_t a0, uint32_t a1,
                                         uint32_t a2, uint32_t a3,
                                         uint32_t b0, uint32_t b1) {
    asm volatile(
        "mma.sync.aligned.m16n8k16.row.col.f32.bf16.bf16.f32 "
        "{%0,%1,%2,%3},{%4,%5,%6,%7},{%8,%9},{%0,%1,%2,%3};"
        : "+f"(c[0]), "+f"(c[1]), "+f"(c[2]), "+f"(c[3])
        : "r"(a0), "r"(a1), "r"(a2), "r"(a3), "r"(b0), "r"(b1));
}
__device__ __forceinline__ void bar_named(int id, int cnt) {
    asm volatile("bar.sync %0, %1;" :: "r"(id), "r"(cnt) : "memory");
}
// Warp-cooperative group-counter poll (consumer warps). Lanes 0-7 own counters.
__device__ __forceinline__ unsigned poll_groups(int lane, unsigned tgt,
                                                unsigned rdy) {
    unsigned ok = 1u;
    if (lane < 8 && !((rdy >> lane) & 1u)) {
        unsigned v;
        asm volatile("ld.acquire.gpu.u32 %0, [%1];"
                     : "=r"(v) : "l"(&g_cnt[lane * 32]) : "memory");
        ok = (v >= tgt) ? 1u : 0u;
    }
    return __ballot_sync(0xffffffffu, ok != 0u);
}

// ---------------------------------------------------------------------------
// Kernel 0: reset
// ---------------------------------------------------------------------------
__global__ void reset_kernel() {
    int idx = blockIdx.x * blockDim.x + threadIdx.x;
    if (idx < 8 * 32) g_cnt[idx] = 0u;
    for (int i = idx; i < 2 * 32768; i += gridDim.x * blockDim.x) g_h[i] = 0u;
}

// ---------------------------------------------------------------------------
// Kernel 1: permute x -> bf16 A-fragment order (one uint4 per thread)
// ---------------------------------------------------------------------------
__global__ __launch_bounds__(256) void permute_x(const float* __restrict__ x) {
    size_t idx = (size_t)blockIdx.x * 256 + threadIdx.x;   // < kT*4096
    int lane = idx & 31;
    int mt   = (idx >> 5) & 3;
    int kcg  = (idx >> 7) & 31;
    int t    = (int)(idx >> 12);
    int r  = mt * 16 + (lane >> 2);                        // batch row
    int k2 = kcg * 16 + 2 * (lane & 3);
    const float* x0 = x + ((size_t)r * kT + t) * kF;
    const float* x8 = x + ((size_t)(r + 8) * kT + t) * kF;
    float2 v00 = *(const float2*)(x0 + k2);
    float2 v10 = *(const float2*)(x8 + k2);
    float2 v01 = *(const float2*)(x0 + k2 + 8);
    float2 v11 = *(const float2*)(x8 + k2 + 8);
    uint4 o;
    o.x = pack_bf16(v00.x, v00.y);
    o.y = pack_bf16(v10.x, v10.y);
    o.z = pack_bf16(v01.x, v01.y);
    o.w = pack_bf16(v11.x, v11.y);
    g_xf[idx] = o;
}

// ---------------------------------------------------------------------------
// Kernel 2: fused persistent LSTM. Warps 0-3: recurrence mma + gates (as R7).
// Warps 4-7: per-step xz = x@Wk+b for this CTA's 32 cols into a 4-deep SMEM
// ring. Producer mma fills the tensor-idle windows of the consumer's serial
// phases. Cross-CTA h dataflow via per-group counters (unchanged).
// ---------------------------------------------------------------------------
extern __shared__ uint32_t fsm[];

__global__ __launch_bounds__(NTHR, 1) void lstm_fused(
    const float* __restrict__ Wr, const float* __restrict__ Wk,
    const float* __restrict__ bias) {
    uint32_t*      Wr_f  = fsm + OFF_WRF;
    uint2*         Wk_f  = (uint2*)(fsm + OFF_WKF);
    float*         ring  = (float*)(fsm + OFF_RING);     // [4][64][34]
    float*         bia_s = (float*)(fsm + OFF_BIAS);
    volatile int*  pflag = (volatile int*)(fsm + OFF_FLAGS);      // [4]
    volatile int*  cflag = (volatile int*)(fsm + OFF_FLAGS + 4);  // [4]

    const int tid = threadIdx.x;
    const int wid = tid >> 5, lid = tid & 31;
    const int u_base = blockIdx.x * 8;
    const int my_group = blockIdx.x >> 4;

    // ---- cooperative init (all 8 warps) ----
    // Wr fragments (16384 u32)
    for (int i = 0; i < 64; i++) {
        int lin = tid + i * NTHR;
        int reg = lin & 1;
        int ll  = (lin >> 1) & 31;
        int kcg = (lin >> 6) & 63;
        int q   = (lin >> 12) & 3;
        int lg = ll >> 2, lq = ll & 3;
        int k  = kcg * 16 + 2 * lq + 8 * reg;
        int col = q * kU + u_base + lg;
        float v0 = Wr[(size_t)k * k4U + col];
        float v1 = Wr[(size_t)(k + 1) * k4U + col];
        Wr_f[((q * 64 + kcg) * 32 + ll) * 2 + reg] = pack_bf16(v0, v1);
    }
    // Wk fragments (4096 uint2): B-frag for producer tiles
    for (int i = 0; i < 16; i++) {
        int lin = tid + i * NTHR;            // < 4096
        int lane = lin & 31;
        int nt   = (lin >> 5) & 3;
        int kcg  = lin >> 7;                 // 0..31
        int gcol = nt * kU + u_base + (lane >> 2);
        int k2   = kcg * 16 + 2 * (lane & 3);
        uint2 bv;
        bv.x = pack_bf16(Wk[(size_t)k2 * k4U + gcol],
                         Wk[(size_t)(k2 + 1) * k4U + gcol]);
        bv.y = pack_bf16(Wk[(size_t)(k2 + 8) * k4U + gcol],
                         Wk[(size_t)(k2 + 9) * k4U + gcol]);
        Wk_f[(kcg * 4 + nt) * 32 + lane] = bv;
    }
    if (tid < 32) bia_s[tid] = bias[(tid >> 3) * kU + u_base + (tid & 7)];
    if (tid < 4) { pflag[tid] = 0; cflag[tid] = 0; }
    __syncthreads();

    if (wid >= 4) {
        // ================= PRODUCER (warps 4-7) =================
        const int pw = wid - 4;              // M-subtile (16 batch rows)
        const int r  = pw * 16 + (lid >> 2);
        const int cl = 2 * (lid & 3);
        for (int tp = 0; tp < kT; tp++) {
            const int s = tp & 3;
            if (tp >= 4) {
                while (cflag[s] < tp - 3) { }
                __threadfence_block();
            }
            float cacc[4][4];
#pragma unroll
            for (int nt = 0; nt < 4; nt++)
#pragma unroll
                for (int k = 0; k < 4; k++) cacc[nt][k] = 0.f;

            const uint4* Ap = g_xf + (size_t)tp * 4096 + pw * 32 + lid;
            uint4 pbuf[4];
#pragma unroll
            for (int i = 0; i < 4; i++) pbuf[i] = __ldcg(Ap + i * 128);
#pragma unroll 4
            for (int kcg = 0; kcg < 32; kcg++) {
                uint4 a = pbuf[kcg & 3];
                if (kcg < 28) pbuf[kcg & 3] = __ldcg(Ap + (kcg + 4) * 128);
#pragma unroll
                for (int nt = 0; nt < 4; nt++) {
                    uint2 bv = Wk_f[(kcg * 4 + nt) * 32 + lid];
                    mma_bf16(cacc[nt], a.x, a.y, a.z, a.w, bv.x, bv.y);
                }
            }
            // epilogue: bias + ring store
            float* rs = ring + (size_t)s * 64 * 34;
#pragma unroll
            for (int nt = 0; nt < 4; nt++) {
                int col = nt * 8 + cl;
                float bx = bia_s[col], by = bia_s[col + 1];
                float2 lo = make_float2(cacc[nt][0] + bx, cacc[nt][1] + by);
                float2 hi = make_float2(cacc[nt][2] + bx, cacc[nt][3] + by);
                *(float2*)&rs[(r)     * 34 + col] = lo;
                *(float2*)&rs[(r + 8) * 34 + col] = hi;
            }
            __threadfence_block();
            bar_named(3, 128);
            if (tid == 128) pflag[s] = tp + 1;
        }
    } else {
        // ================= CONSUMER (warps 0-3) =================
        const int w = wid, l = lid;
        const int grp = l >> 2, qd = l & 3;
        const int b0 = w * 16 + grp;         // batch rows b0, b0+8
        const int j0 = 2 * qd;               // units j0, j0+1
        const int kcg_w = blockIdx.x >> 1;
        const int hi_w  = blockIdx.x & 1;

        float cst[4] = {0.f, 0.f, 0.f, 0.f};

        for (int t = 0; t < kT; t++) {
            const uint4* Ag = (const uint4*)(g_h + (size_t)(t & 1) * 32768);
            uint32_t*  hwrt = g_h + (size_t)((t + 1) & 1) * 32768;

            unsigned tgt = 16u * (unsigned)t;
            unsigned rdy = (t == 0) ? 0xffffffffu : 0u;
            const int g0 = my_group;
            while (!((rdy >> g0) & 1u)) rdy = poll_groups(l, tgt, rdy);

            float acc[4][2][4];
#pragma unroll
            for (int q = 0; q < 4; q++)
#pragma unroll
                for (int p = 0; p < 2; p++)
#pragma unroll
                    for (int k = 0; k < 4; k++) acc[q][p][k] = 0.f;

            uint4 abuf[8];
#pragma unroll
            for (int i = 0; i < 8; i++)
                abuf[i] = __ldcg(Ag + (8 * g0 + i) * 128 + tid);

            for (int ch = 0; ch < 8; ch++) {
                const int g  = (ch + my_group) & 7;
                const int gn = (g + 1) & 7;
                if (ch < 7)
                    while (!((rdy >> gn) & 1u)) rdy = poll_groups(l, tgt, rdy);
#pragma unroll
                for (int k8 = 0; k8 < 8; k8++) {
                    uint4 a = abuf[k8];
                    if (ch < 7) abuf[k8] = __ldcg(Ag + (8 * gn + k8) * 128 + tid);
                    int kcg = 8 * g + k8;
#pragma unroll
                    for (int q = 0; q < 4; q++) {
                        uint2 bv = *(const uint2*)&Wr_f[((q * 64 + kcg) * 32 + l) * 2];
                        mma_bf16(acc[q][k8 & 1], a.x, a.y, a.z, a.w, bv.x, bv.y);
                    }
                }
            }

            // xz from SMEM ring (producer runs ahead; wait is usually instant)
            const int s = t & 3;
            while (pflag[s] < t + 1) { }
            __threadfence_block();
            const float* rs = ring + (size_t)s * 64 * 34;
            float2 xz[2][4];
#pragma unroll
            for (int r2 = 0; r2 < 2; r2++)
#pragma unroll
                for (int q = 0; q < 4; q++)
                    xz[r2][q] = *(const float2*)&rs[(b0 + 8 * r2) * 34 + q * 8 + j0];

            // gate phase (registers only)
#pragma unroll
            for (int r2 = 0; r2 < 2; r2++) {
                float hv[2];
#pragma unroll
                for (int d = 0; d < 2; d++) {
                    int idx = 2 * r2 + d;
                    float zi = acc[0][0][idx] + acc[0][1][idx] + (d ? xz[r2][0].y : xz[r2][0].x);
                    float zf = acc[1][0][idx] + acc[1][1][idx] + (d ? xz[r2][1].y : xz[r2][1].x);
                    float zg = acc[2][0][idx] + acc[2][1][idx] + (d ? xz[r2][2].y : xz[r2][2].x);
                    float zo = acc[3][0][idx] + acc[3][1][idx] + (d ? xz[r2][3].y : xz[r2][3].x);
                    float ig = sigmoid_fast(zi);
                    float fg = sigmoid_fast(zf);
                    float gg = tanh_fast(zg);
                    float og = sigmoid_fast(zo);
                    float cv = fg * cst[idx] + ig * gg;
                    cst[idx] = cv;
                    hv[d] = og * tanh_fast(cv);
                }
                hwrt[(kcg_w * 128 + tid) * 4 + 2 * hi_w + r2] = pack_bf16(hv[0], hv[1]);
            }

            // publish h + free ring stage
            __threadfence();
            bar_named(2, 128);
            if (tid == 0) {
                atomicAdd(&g_cnt[my_group * 32], 1u);
                cflag[s] = t + 1;
            }
        }
    }
}

// ---------------------------------------------------------------------------
// Kernel 3: logits = h_last @ Wd + bd; softmax per row (permuted bf16 buf 0)
// ---------------------------------------------------------------------------
__device__ __forceinline__ float h_read_b0(int b, int u) {
    uint32_t v = g_h[((u >> 4) * 128 + (b >> 4) * 32 + (b & 7) * 4 + ((u & 7) >> 1)) * 4
                     + 2 * ((u >> 3) & 1) + ((b >> 3) & 1)];
    return __uint_as_float((u & 1) ? (v & 0xffff0000u) : (v << 16));
}

__global__ __launch_bounds__(256) void dense_softmax_kernel(
    const float* __restrict__ Wd, const float* __restrict__ bd,
    float* __restrict__ out) {
    __shared__ float hrow[kU];
    __shared__ float red[256];

    const int b   = blockIdx.x;
    const int tid = threadIdx.x;
    for (int u = tid; u < kU; u += 256) hrow[u] = h_read_b0(b, u);
    __syncthreads();

    float acc[4] = {0.f, 0.f, 0.f, 0.f};
    const int j0 = tid * 4;
    const bool active = (j0 < kC);
    if (active) {
        const float* wp = Wd + j0;
#pragma unroll 4
        for (int k = 0; k < kU; k++) {
            float4 wv = *(const float4*)(wp + (size_t)k * kC);
            float  hk = hrow[k];
            acc[0] = fmaf(hk, wv.x, acc[0]);
            acc[1] = fmaf(hk, wv.y, acc[1]);
            acc[2] = fmaf(hk, wv.z, acc[2]);
            acc[3] = fmaf(hk, wv.w, acc[3]);
        }
        float4 bv = *(const float4*)&bd[j0];
        acc[0] += bv.x; acc[1] += bv.y; acc[2] += bv.z; acc[3] += bv.w;
    }

    float m = active ? fmaxf(fmaxf(acc[0], acc[1]), fmaxf(acc[2], acc[3]))
                     : -INFINITY;
    red[tid] = m;
    __syncthreads();
    for (int s = 128; s > 0; s >>= 1) {
        if (tid < s) red[tid] = fmaxf(red[tid], red[tid + s]);
        __syncthreads();
    }
    float mx = red[0];
    __syncthreads();

    float e[4] = {0.f, 0.f, 0.f, 0.f};
    float psum = 0.f;
    if (active) {
#pragma unroll
        for (int cc = 0; cc < 4; cc++) { e[cc] = expf(acc[cc] - mx); psum += e[cc]; }
    }
    red[tid] = psum;
    __syncthreads();
    for (int s = 128; s > 0; s >>= 1) {
        if (tid < s) red[tid] += red[tid + s];
        __syncthreads();
    }
    float inv = 1.f / red[0];
    if (active) {
#pragma unroll
        for (int cc = 0; cc < 4; cc++) out[(size_t)b * kC + j0 + cc] = e[cc] * inv;
    }
}

// ---------------------------------------------------------------------------
// Launch
// ---------------------------------------------------------------------------
extern "C" void kernel_launch(void* const* d_in, const int* in_sizes, int n_in,
                              void* d_out, int out_size) {
    const float* x    = (const float*)d_in[0];
    const float* Wk   = (const float*)d_in[1];
    const float* Wr   = (const float*)d_in[2];
    const float* bias = (const float*)d_in[3];
    const float* Wd   = (const float*)d_in[4];
    const float* bd   = (const float*)d_in[5];
    float* out = (float*)d_out;

    const int smem_bytes = SMEM_U32 * (int)sizeof(uint32_t);   // 133280
    cudaFuncSetAttribute(lstm_fused, cudaFuncAttributeMaxDynamicSharedMemorySize,
                         smem_bytes);

    reset_kernel<<<64, 256>>>();
    permute_x<<<(int)((size_t)kT * 4096 / 256), 256>>>(x);
    lstm_fused<<<NCTA, NTHR, smem_bytes>>>(Wr, Wk, bias);
    dense_softmax_kernel<<<kB, 256>>>(Wd, bd, out);
}